// round 16
// baseline (speedup 1.0000x reference)
#include <cuda_runtime.h>
#include <cuda_fp16.h>
#include <cstdint>

#define B_ 4
#define N_ 2048
#define E_ 1024
#define H_ 16
#define D_ 64
#define SCALE_LOG2E 0.18033688f  // 0.125 * log2(e)
#define MTOT (B_ * N_)           // 8192

// ---------------------------------------------------------------------------
// Scratch (allocation-free rule: __device__ globals)
// ---------------------------------------------------------------------------
__device__ __half g_xq[(size_t)MTOT * E_];
__device__ __half g_xk[(size_t)MTOT * E_];
__device__ __half g_xv[(size_t)MTOT * E_];

__device__ __half g_Q[(size_t)MTOT * E_];
__device__ __half g_K[(size_t)MTOT * E_];
__device__ __half g_V[(size_t)MTOT * E_];
__device__ __half g_A[(size_t)MTOT * E_];

__device__ __half g_Wq[(size_t)E_ * E_];
__device__ __half g_Wk[(size_t)E_ * E_];
__device__ __half g_Wv[(size_t)E_ * E_];
__device__ __half g_Wo[(size_t)E_ * E_];

// ---------------------------------------------------------------------------
// helpers
// ---------------------------------------------------------------------------
__device__ __forceinline__ uint32_t smem_u32(const void* p) {
    uint32_t a;
    asm("{ .reg .u64 t; cvta.to.shared.u64 t, %1; cvt.u32.u64 %0, t; }"
        : "=r"(a) : "l"(p));
    return a;
}
__device__ __forceinline__ void cp16(uint32_t sa, const void* ga) {
    asm volatile("cp.async.cg.shared.global [%0], [%1], 16;"
                 :: "r"(sa), "l"(ga));
}
__device__ __forceinline__ void cp_commit() {
    asm volatile("cp.async.commit_group;");
}
__device__ __forceinline__ void cp_wait1() {
    asm volatile("cp.async.wait_group 1;");
}
__device__ __forceinline__ void cp_wait0() {
    asm volatile("cp.async.wait_group 0;");
}
__device__ __forceinline__ void ldmx4(uint32_t& r0, uint32_t& r1,
                                      uint32_t& r2, uint32_t& r3, uint32_t a) {
    asm volatile("ldmatrix.sync.aligned.m8n8.x4.shared.b16 {%0,%1,%2,%3}, [%4];"
                 : "=r"(r0), "=r"(r1), "=r"(r2), "=r"(r3) : "r"(a));
}
__device__ __forceinline__ void ldmx4t(uint32_t& r0, uint32_t& r1,
                                       uint32_t& r2, uint32_t& r3, uint32_t a) {
    asm volatile("ldmatrix.sync.aligned.m8n8.x4.trans.shared.b16 {%0,%1,%2,%3}, [%4];"
                 : "=r"(r0), "=r"(r1), "=r"(r2), "=r"(r3) : "r"(a));
}
__device__ __forceinline__ void mma16816(float* d, const uint32_t* a,
                                         const uint32_t* b) {
    asm volatile(
        "mma.sync.aligned.m16n8k16.row.col.f32.f16.f16.f32 "
        "{%0,%1,%2,%3}, {%4,%5,%6,%7}, {%8,%9}, {%0,%1,%2,%3};"
        : "+f"(d[0]), "+f"(d[1]), "+f"(d[2]), "+f"(d[3])
        : "r"(a[0]), "r"(a[1]), "r"(a[2]), "r"(a[3]), "r"(b[0]), "r"(b[1]));
}
__device__ __forceinline__ uint32_t pack2h(float a, float b) {
    __half2 h = __floats2half2_rn(a, b);
    return *(uint32_t*)&h;
}

// ldmatrix.x4 lane address within a [rows][72 halfs] (144B-stride) tile.
// r0: tile row of the 16x16 block; c0: tile column in halfs.
__device__ __forceinline__ uint32_t lda(uint32_t base, int r0, int c0) {
    int L = threadIdx.x & 31;
    int mat = L >> 3;
    int r = r0 + (L & 7) + ((mat & 1) << 3);
    int c = c0 + ((mat >> 1) << 3);
    return base + (uint32_t)r * 144 + c * 2;
}

// ---------------------------------------------------------------------------
// Prepass: fp32 -> fp16, fused over multiple tensors (blockIdx.y selects).
// ---------------------------------------------------------------------------
__global__ __launch_bounds__(256) void convert_h3(
    const float* __restrict__ s0, const float* __restrict__ s1,
    const float* __restrict__ s2,
    __half* __restrict__ d0, __half* __restrict__ d1,
    __half* __restrict__ d2, int n4)
{
    int i = blockIdx.x * 256 + threadIdx.x;
    if (i >= n4) return;
    int t = blockIdx.y;
    const float* src = (t == 0) ? s0 : (t == 1) ? s1 : s2;
    __half* dst = (t == 0) ? d0 : (t == 1) ? d1 : d2;
    float4 v = ((const float4*)src)[i];
    ((uint2*)dst)[i] = make_uint2(pack2h(v.x, v.y), pack2h(v.z, v.w));
}
__global__ __launch_bounds__(256) void convert_h4(
    const float* __restrict__ s0, const float* __restrict__ s1,
    const float* __restrict__ s2, const float* __restrict__ s3,
    __half* __restrict__ d0, __half* __restrict__ d1,
    __half* __restrict__ d2, __half* __restrict__ d3, int n4)
{
    int i = blockIdx.x * 256 + threadIdx.x;
    if (i >= n4) return;
    int t = blockIdx.y;
    const float* src = (t == 0) ? s0 : (t == 1) ? s1 : (t == 2) ? s2 : s3;
    __half* dst = (t == 0) ? d0 : (t == 1) ? d1 : (t == 2) ? d2 : d3;
    float4 v = ((const float4*)src)[i];
    ((uint2*)dst)[i] = make_uint2(pack2h(v.x, v.y), pack2h(v.z, v.w));
}

// ===========================================================================
// GEMM tiling: CTA 128x128, BKC=64 (16 chunks), 2-stage cp.async.
// Tiles stored with 144-byte row stride (72 halfs), conflict-free ldmatrix.
// ===========================================================================
#define BM 128
#define BN 128
#define BKC 64
#define KTOT 1024
#define NCHUNK (KTOT / BKC)        // 16
#define GTILE_B (128 * 144)        // 18432
#define GSTAGE (2 * GTILE_B)       // 36864
#define GSMEM_SZ (2 * GSTAGE)      // 73728 -> 2 CTAs/SM

// ---------------------------------------------------------------------------
// Core 1-product GEMM body (device inline): acc = X @ W^T over K=1024.
// ---------------------------------------------------------------------------
__device__ __forceinline__ void gemm_body(
    const char* tbX, const char* tbW, uint32_t smb, float acc[4][4][4])
{
    const int tid = threadIdx.x;
    const int w = tid >> 5;
    const int wm = w >> 2;
    const int wn = w & 3;

    auto issue = [&](int c, int s) {
#pragma unroll
        for (int i = 0; i < 8; i++) {
            int sid = tid + 256 * i;          // 0..2047
            int tile = sid >> 10;             // 0 X, 1 W
            int r = (sid >> 3) & 127;
            int seg = sid & 7;
            const char* base = tile ? tbW : tbX;
            uint32_t sa = smb + (uint32_t)s * GSTAGE + (uint32_t)tile * GTILE_B
                        + (uint32_t)r * 144 + seg * 16;
            const char* ga = base + (size_t)r * (KTOT * 2) + c * (BKC * 2) + seg * 16;
            cp16(sa, ga);
        }
        cp_commit();
    };

    issue(0, 0);

    for (int c = 0; c < NCHUNK; c++) {
        const int st = c & 1;
        if (c + 1 < NCHUNK) {
            issue(c + 1, st ^ 1);
            cp_wait1();
        } else {
            cp_wait0();
        }
        __syncthreads();

        const uint32_t bX = smb + (uint32_t)st * GSTAGE;
        const uint32_t bW = bX + GTILE_B;

#pragma unroll
        for (int ks = 0; ks < 4; ks++) {
            uint32_t ax[4][4], bw[4][2];
#pragma unroll
            for (int mt = 0; mt < 4; mt++)
                ldmx4(ax[mt][0], ax[mt][1], ax[mt][2], ax[mt][3],
                      lda(bX, wm * 64 + mt * 16, ks * 16));
#pragma unroll
            for (int np = 0; np < 2; np++) {
                uint32_t r0, r1, r2, r3;
                ldmx4(r0, r1, r2, r3, lda(bW, wn * 32 + np * 16, ks * 16));
                bw[np * 2 + 0][0] = r0; bw[np * 2 + 0][1] = r2;
                bw[np * 2 + 1][0] = r1; bw[np * 2 + 1][1] = r3;
            }
#pragma unroll
            for (int mt = 0; mt < 4; mt++)
#pragma unroll
                for (int nt = 0; nt < 4; nt++)
                    mma16816(acc[mt][nt], ax[mt], bw[nt]);
        }
        __syncthreads();
    }
}

// ===========================================================================
// Fused Q/K/V projection: blockIdx.z selects (X, W, out, scale); fp16 out.
// ===========================================================================
__global__ __launch_bounds__(256, 2) void gemm_proj(
    const __half* __restrict__ xq, const __half* __restrict__ xk,
    const __half* __restrict__ xv,
    const __half* __restrict__ Wq, const __half* __restrict__ Wk,
    const __half* __restrict__ Wv,
    __half* __restrict__ Q, __half* __restrict__ K, __half* __restrict__ V)
{
    extern __shared__ char dynsm[];
    const uint32_t smb = smem_u32(dynsm);
    const int which = blockIdx.z;
    const int bm = blockIdx.y * BM;
    const int bn = blockIdx.x * BN;

    const __half* X = (which == 0) ? xq : (which == 1) ? xk : xv;
    const __half* W = (which == 0) ? Wq : (which == 1) ? Wk : Wv;
    __half* O = (which == 0) ? Q : (which == 1) ? K : V;
    const float scale = (which == 0) ? SCALE_LOG2E : 1.0f;

    float acc[4][4][4];
#pragma unroll
    for (int i = 0; i < 4; i++)
#pragma unroll
        for (int j = 0; j < 4; j++)
#pragma unroll
            for (int t = 0; t < 4; t++) acc[i][j][t] = 0.f;

    gemm_body((const char*)(X + (size_t)bm * KTOT),
              (const char*)(W + (size_t)bn * KTOT), smb, acc);

    const int tid = threadIdx.x;
    const int w = tid >> 5;
    const int wm = w >> 2;
    const int wn = w & 3;
    const int lid = tid & 31;
    const int grp = lid >> 2;
    const int tig = lid & 3;
#pragma unroll
    for (int mt = 0; mt < 4; mt++) {
#pragma unroll
        for (int nt = 0; nt < 4; nt++) {
            int row = bm + wm * 64 + mt * 16 + grp;
            int col = bn + wn * 32 + nt * 8 + tig * 2;
            *(uint32_t*)(O + (size_t)row * E_ + col) =
                pack2h(acc[mt][nt][0] * scale, acc[mt][nt][1] * scale);
            *(uint32_t*)(O + (size_t)(row + 8) * E_ + col) =
                pack2h(acc[mt][nt][2] * scale, acc[mt][nt][3] * scale);
        }
    }
}

// ===========================================================================
// Output projection: C = A @ Wo^T + bias, fp32 out.
// ===========================================================================
__global__ __launch_bounds__(256, 2) void gemm_out(
    const __half* __restrict__ X, const __half* __restrict__ W,
    const float* __restrict__ bias, float* __restrict__ Cf)
{
    extern __shared__ char dynsm[];
    const uint32_t smb = smem_u32(dynsm);
    const int bm = blockIdx.y * BM;
    const int bn = blockIdx.x * BN;

    float acc[4][4][4];
#pragma unroll
    for (int i = 0; i < 4; i++)
#pragma unroll
        for (int j = 0; j < 4; j++)
#pragma unroll
            for (int t = 0; t < 4; t++) acc[i][j][t] = 0.f;

    gemm_body((const char*)(X + (size_t)bm * KTOT),
              (const char*)(W + (size_t)bn * KTOT), smb, acc);

    const int tid = threadIdx.x;
    const int w = tid >> 5;
    const int wm = w >> 2;
    const int wn = w & 3;
    const int lid = tid & 31;
    const int grp = lid >> 2;
    const int tig = lid & 3;
#pragma unroll
    for (int mt = 0; mt < 4; mt++) {
#pragma unroll
        for (int nt = 0; nt < 4; nt++) {
            int row = bm + wm * 64 + mt * 16 + grp;
            int col = bn + wn * 32 + nt * 8 + tig * 2;
            float b0 = bias[col], b1 = bias[col + 1];
            *(float2*)(Cf + (size_t)row * E_ + col) =
                make_float2(acc[mt][nt][0] + b0, acc[mt][nt][1] + b1);
            *(float2*)(Cf + (size_t)(row + 8) * E_ + col) =
                make_float2(acc[mt][nt][2] + b0, acc[mt][nt][3] + b1);
        }
    }
}

// ===========================================================================
// Tensor-core causal flash attention, fp16 single-product.
// q-tile 128 rows (8 warps); S = Q K^T; O = P V; exp2 softmax.
// K/V triple-buffered cp.async (wait_group 1 hides stage latency).
// ===========================================================================
#define AQ_TILE (128 * 144)        // 18432
#define AKV_TILE (64 * 144)        // 9216
#define AOFF_Q 0
#define AOFF_ST AQ_TILE            // 18432
#define ASTAGE (2 * AKV_TILE)      // 18432
#define ASMEM (AOFF_ST + 3 * ASTAGE)  // 73728 -> 2 CTAs/SM

__global__ __launch_bounds__(256, 2) void attn_mma(
    const __half* __restrict__ Q, const __half* __restrict__ K,
    const __half* __restrict__ V, __half* __restrict__ O)
{
    extern __shared__ char dynsm[];
    const uint32_t smb = smem_u32(dynsm);
    const int tid = threadIdx.x;
    const int w = tid >> 5;
    const int lid = tid & 31;
    const int grp = lid >> 2;
    const int tig = lid & 3;
    const int iblk = (gridDim.x - 1) - blockIdx.x;   // heavy blocks first
    const int h = blockIdx.y;
    const int b = blockIdx.z;
    const int qbase = iblk * 128;
    const int jmax = 2 * iblk + 1;
    const size_t bN = (size_t)b * N_;

    auto issue_stage = [&](int s, int kbase) {
#pragma unroll
        for (int i = 0; i < 4; i++) {
            int sid = tid + 256 * i;          // 0..1023
            int tile = sid >> 9;              // 0 K, 1 V
            int r = (sid >> 3) & 63;
            int seg = sid & 7;
            const __half* gp = tile ? V : K;
            const char* ga = (const char*)(gp + (bN + kbase + r) * E_ + h * 64)
                           + seg * 16;
            cp16(smb + AOFF_ST + (uint32_t)s * ASTAGE + (uint32_t)tile * AKV_TILE
                 + (uint32_t)r * 144 + seg * 16, ga);
        }
        cp_commit();
    };

    // prologue: Q tile + KV stage 0 (one group), then KV stage 1 (2nd group)
    {
#pragma unroll
        for (int i = 0; i < 4; i++) {
            int sid = tid + 256 * i;          // 0..1023
            int r = sid >> 3;
            int seg = sid & 7;
            const char* ga = (const char*)(Q + (bN + qbase + r) * E_ + h * 64)
                           + seg * 16;
            cp16(smb + AOFF_Q + (uint32_t)r * 144 + seg * 16, ga);
        }
    }
    issue_stage(0, 0);        // group: Q + stage0
    issue_stage(1, 64);       // group: stage1 (jmax >= 1 always)

    uint32_t qq[4][4];
    float o[8][4];
#pragma unroll
    for (int t = 0; t < 8; t++)
#pragma unroll
        for (int c = 0; c < 4; c++) o[t][c] = 0.f;
    float mr0 = -1e30f, mr1 = -1e30f, lr0 = 0.f, lr1 = 0.f;

    for (int j = 0; j <= jmax; j++) {
        if (j < jmax) cp_wait1(); else cp_wait0();
        __syncthreads();
        if (j == 0) {
#pragma unroll
            for (int kc = 0; kc < 4; kc++)
                ldmx4(qq[kc][0], qq[kc][1], qq[kc][2], qq[kc][3],
                      lda(smb + AOFF_Q, w * 16, kc * 16));
        }
        if (j + 2 <= jmax) issue_stage((j + 2) % 3, (j + 2) * 64);

        const uint32_t bK = smb + AOFF_ST + (uint32_t)(j % 3) * ASTAGE;
        const uint32_t bV = bK + AKV_TILE;

        // ---- S = Q K^T (hoisted K fragments) ----
        float s[8][4];
#pragma unroll
        for (int t = 0; t < 8; t++)
#pragma unroll
            for (int c = 0; c < 4; c++) s[t][c] = 0.f;
#pragma unroll
        for (int kc = 0; kc < 4; kc++) {
            uint32_t bk[8][2];
#pragma unroll
            for (int np = 0; np < 4; np++) {
                uint32_t r0, r1, r2, r3;
                ldmx4(r0, r1, r2, r3, lda(bK, np * 16, kc * 16));
                bk[np * 2 + 0][0] = r0; bk[np * 2 + 0][1] = r2;
                bk[np * 2 + 1][0] = r1; bk[np * 2 + 1][1] = r3;
            }
#pragma unroll
            for (int t = 0; t < 8; t++) mma16816(s[t], qq[kc], bk[t]);
        }

        // ---- causal mask (only kv-blocks crossing the diagonal) ----
        if (j >= 2 * iblk) {
            const int row0 = qbase + w * 16 + grp;
            const int row1 = row0 + 8;
            const int cb = j * 64;
#pragma unroll
            for (int t = 0; t < 8; t++) {
                int col = cb + t * 8 + 2 * tig;
                if (col > row0) s[t][0] = -1e30f;
                if (col + 1 > row0) s[t][1] = -1e30f;
                if (col > row1) s[t][2] = -1e30f;
                if (col + 1 > row1) s[t][3] = -1e30f;
            }
        }

        // ---- online softmax (base-2) ----
        float m0 = -1e30f, m1 = -1e30f;
#pragma unroll
        for (int t = 0; t < 8; t++) {
            m0 = fmaxf(m0, fmaxf(s[t][0], s[t][1]));
            m1 = fmaxf(m1, fmaxf(s[t][2], s[t][3]));
        }
        m0 = fmaxf(m0, __shfl_xor_sync(0xffffffffu, m0, 1));
        m0 = fmaxf(m0, __shfl_xor_sync(0xffffffffu, m0, 2));
        m1 = fmaxf(m1, __shfl_xor_sync(0xffffffffu, m1, 1));
        m1 = fmaxf(m1, __shfl_xor_sync(0xffffffffu, m1, 2));
        float mn0 = fmaxf(mr0, m0), mn1 = fmaxf(mr1, m1);
        float a0 = exp2f(mr0 - mn0), a1 = exp2f(mr1 - mn1);
        mr0 = mn0; mr1 = mn1;
        float sum0 = 0.f, sum1 = 0.f;
#pragma unroll
        for (int t = 0; t < 8; t++) {
            s[t][0] = exp2f(s[t][0] - mn0);
            s[t][1] = exp2f(s[t][1] - mn0);
            s[t][2] = exp2f(s[t][2] - mn1);
            s[t][3] = exp2f(s[t][3] - mn1);
            sum0 += s[t][0] + s[t][1];
            sum1 += s[t][2] + s[t][3];
        }
        sum0 += __shfl_xor_sync(0xffffffffu, sum0, 1);
        sum0 += __shfl_xor_sync(0xffffffffu, sum0, 2);
        sum1 += __shfl_xor_sync(0xffffffffu, sum1, 1);
        sum1 += __shfl_xor_sync(0xffffffffu, sum1, 2);
        lr0 = lr0 * a0 + sum0;
        lr1 = lr1 * a1 + sum1;
#pragma unroll
        for (int t = 0; t < 8; t++) {
            o[t][0] *= a0; o[t][1] *= a0;
            o[t][2] *= a1; o[t][3] *= a1;
        }

        // ---- P: C-frag -> A-frag, single fp16 ----
        uint32_t ph[4][4];
#pragma unroll
        for (int kc = 0; kc < 4; kc++) {
            ph[kc][0] = pack2h(s[2 * kc][0], s[2 * kc][1]);
            ph[kc][1] = pack2h(s[2 * kc][2], s[2 * kc][3]);
            ph[kc][2] = pack2h(s[2 * kc + 1][0], s[2 * kc + 1][1]);
            ph[kc][3] = pack2h(s[2 * kc + 1][2], s[2 * kc + 1][3]);
        }

        // ---- O += P V (hoisted V fragments) ----
#pragma unroll
        for (int kc = 0; kc < 4; kc++) {
            uint32_t vv[8][2];
#pragma unroll
            for (int nd = 0; nd < 4; nd++) {
                uint32_t r0, r1, r2, r3;
                ldmx4t(r0, r1, r2, r3, lda(bV, kc * 16, nd * 16));
                vv[nd * 2 + 0][0] = r0; vv[nd * 2 + 0][1] = r1;
                vv[nd * 2 + 1][0] = r2; vv[nd * 2 + 1][1] = r3;
            }
#pragma unroll
            for (int t = 0; t < 8; t++) mma16816(o[t], ph[kc], vv[t]);
        }
    }

    // ---- epilogue: normalize, single fp16, store [B,N,E] ----
    const float i0 = 1.f / lr0, i1 = 1.f / lr1;
    const int qr0 = qbase + w * 16 + grp;
    const size_t ro0 = (bN + qr0) * E_;
    const size_t ro1 = (bN + qr0 + 8) * E_;
#pragma unroll
    for (int t = 0; t < 8; t++) {
        int col = h * 64 + t * 8 + 2 * tig;
        *(uint32_t*)(O + ro0 + col) = pack2h(o[t][0] * i0, o[t][1] * i0);
        *(uint32_t*)(O + ro1 + col) = pack2h(o[t][2] * i1, o[t][3] * i1);
    }
}

// ---------------------------------------------------------------------------
extern "C" void kernel_launch(void* const* d_in, const int* in_sizes, int n_in,
                              void* d_out, int out_size)
{
    const float* xq = (const float*)d_in[0];
    const float* xk = (const float*)d_in[1];
    const float* xv = (const float*)d_in[2];
    // d_in[3] = attn_mask (causal, recomputed analytically) — unused
    const float* Wq = (const float*)d_in[4];
    const float* Wk = (const float*)d_in[5];
    const float* Wv = (const float*)d_in[6];
    const float* Wo = (const float*)d_in[7];
    const float* bo = (const float*)d_in[8];
    float* out = (float*)d_out;

    __half *xqp, *xkp, *xvp;
    __half *Qb, *Kb, *Vb, *Ab;
    __half *Wqh, *Wkh, *Wvh, *Woh;
    cudaGetSymbolAddress((void**)&xqp, g_xq);
    cudaGetSymbolAddress((void**)&xkp, g_xk);
    cudaGetSymbolAddress((void**)&xvp, g_xv);
    cudaGetSymbolAddress((void**)&Qb, g_Q);
    cudaGetSymbolAddress((void**)&Kb, g_K);
    cudaGetSymbolAddress((void**)&Vb, g_V);
    cudaGetSymbolAddress((void**)&Ab, g_A);
    cudaGetSymbolAddress((void**)&Wqh, g_Wq);
    cudaGetSymbolAddress((void**)&Wkh, g_Wk);
    cudaGetSymbolAddress((void**)&Wvh, g_Wv);
    cudaGetSymbolAddress((void**)&Woh, g_Wo);

    cudaFuncSetAttribute(gemm_proj, cudaFuncAttributeMaxDynamicSharedMemorySize,
                         GSMEM_SZ);
    cudaFuncSetAttribute(gemm_out, cudaFuncAttributeMaxDynamicSharedMemorySize,
                         GSMEM_SZ);
    cudaFuncSetAttribute(attn_mma, cudaFuncAttributeMaxDynamicSharedMemorySize,
                         ASMEM);

    // Prepass conversions (fused: 2 launches)
    const int nx4 = MTOT * E_ / 4;
    const int nw4 = E_ * E_ / 4;
    dim3 cx(nx4 / 256, 3);
    convert_h3<<<cx, 256>>>(xq, xk, xv, xqp, xkp, xvp, nx4);
    dim3 cw(nw4 / 256, 4);
    convert_h4<<<cw, 256>>>(Wq, Wk, Wv, Wo, Wqh, Wkh, Wvh, Woh, nw4);

    // Fused Q/K/V projections (one launch, z selects which)
    dim3 gblock(256);
    dim3 pgrid(E_ / BN, MTOT / BM, 3);     // (8, 64, 3)
    gemm_proj<<<pgrid, gblock, GSMEM_SZ>>>(xqp, xkp, xvp, Wqh, Wkh, Wvh,
                                           Qb, Kb, Vb);

    dim3 agrid(N_ / 128, H_, B_);          // (16, 16, 4)
    attn_mma<<<agrid, 256, ASMEM>>>(Qb, Kb, Vb, Ab);

    // Output projection -> fp32 + bias
    dim3 ogrid(E_ / BN, MTOT / BM);        // (8, 64)
    gemm_out<<<ogrid, gblock, GSMEM_SZ>>>(Ab, Woh, bo, out);
}

// round 17
// speedup vs baseline: 1.4068x; 1.4068x over previous
#include <cuda_runtime.h>
#include <cuda_fp16.h>
#include <cstdint>

#define B_ 4
#define N_ 2048
#define E_ 1024
#define H_ 16
#define D_ 64
#define SCALE_LOG2E 0.18033688f  // 0.125 * log2(e)
#define MTOT (B_ * N_)           // 8192

// ---------------------------------------------------------------------------
// Scratch (allocation-free rule: __device__ globals)
// ---------------------------------------------------------------------------
__device__ __half g_xq[(size_t)MTOT * E_];
__device__ __half g_xk[(size_t)MTOT * E_];
__device__ __half g_xv[(size_t)MTOT * E_];

__device__ __half g_Q[(size_t)MTOT * E_];
__device__ __half g_K[(size_t)MTOT * E_];
__device__ __half g_V[(size_t)MTOT * E_];
__device__ __half g_A[(size_t)MTOT * E_];

__device__ __half g_Wq[(size_t)E_ * E_];
__device__ __half g_Wk[(size_t)E_ * E_];
__device__ __half g_Wv[(size_t)E_ * E_];
__device__ __half g_Wo[(size_t)E_ * E_];

// ---------------------------------------------------------------------------
// helpers
// ---------------------------------------------------------------------------
__device__ __forceinline__ uint32_t smem_u32(const void* p) {
    uint32_t a;
    asm("{ .reg .u64 t; cvta.to.shared.u64 t, %1; cvt.u32.u64 %0, t; }"
        : "=r"(a) : "l"(p));
    return a;
}
__device__ __forceinline__ void cp16(uint32_t sa, const void* ga) {
    asm volatile("cp.async.cg.shared.global [%0], [%1], 16;"
                 :: "r"(sa), "l"(ga));
}
__device__ __forceinline__ void cp_commit() {
    asm volatile("cp.async.commit_group;");
}
__device__ __forceinline__ void cp_wait1() {
    asm volatile("cp.async.wait_group 1;");
}
__device__ __forceinline__ void cp_wait0() {
    asm volatile("cp.async.wait_group 0;");
}
__device__ __forceinline__ void ldmx4(uint32_t& r0, uint32_t& r1,
                                      uint32_t& r2, uint32_t& r3, uint32_t a) {
    asm volatile("ldmatrix.sync.aligned.m8n8.x4.shared.b16 {%0,%1,%2,%3}, [%4];"
                 : "=r"(r0), "=r"(r1), "=r"(r2), "=r"(r3) : "r"(a));
}
__device__ __forceinline__ void ldmx4t(uint32_t& r0, uint32_t& r1,
                                       uint32_t& r2, uint32_t& r3, uint32_t a) {
    asm volatile("ldmatrix.sync.aligned.m8n8.x4.trans.shared.b16 {%0,%1,%2,%3}, [%4];"
                 : "=r"(r0), "=r"(r1), "=r"(r2), "=r"(r3) : "r"(a));
}
__device__ __forceinline__ void mma16816(float* d, const uint32_t* a,
                                         const uint32_t* b) {
    asm volatile(
        "mma.sync.aligned.m16n8k16.row.col.f32.f16.f16.f32 "
        "{%0,%1,%2,%3}, {%4,%5,%6,%7}, {%8,%9}, {%0,%1,%2,%3};"
        : "+f"(d[0]), "+f"(d[1]), "+f"(d[2]), "+f"(d[3])
        : "r"(a[0]), "r"(a[1]), "r"(a[2]), "r"(a[3]), "r"(b[0]), "r"(b[1]));
}
__device__ __forceinline__ uint32_t pack2h(float a, float b) {
    __half2 h = __floats2half2_rn(a, b);
    return *(uint32_t*)&h;
}

// ---------------------------------------------------------------------------
// Prepass: fp32 -> fp16, fused over multiple tensors (blockIdx.y selects).
// ---------------------------------------------------------------------------
__global__ __launch_bounds__(256) void convert_h3(
    const float* __restrict__ s0, const float* __restrict__ s1,
    const float* __restrict__ s2,
    __half* __restrict__ d0, __half* __restrict__ d1,
    __half* __restrict__ d2, int n4)
{
    int i = blockIdx.x * 256 + threadIdx.x;
    if (i >= n4) return;
    int t = blockIdx.y;
    const float* src = (t == 0) ? s0 : (t == 1) ? s1 : s2;
    __half* dst = (t == 0) ? d0 : (t == 1) ? d1 : d2;
    float4 v = ((const float4*)src)[i];
    ((uint2*)dst)[i] = make_uint2(pack2h(v.x, v.y), pack2h(v.z, v.w));
}
__global__ __launch_bounds__(256) void convert_h4(
    const float* __restrict__ s0, const float* __restrict__ s1,
    const float* __restrict__ s2, const float* __restrict__ s3,
    __half* __restrict__ d0, __half* __restrict__ d1,
    __half* __restrict__ d2, __half* __restrict__ d3, int n4)
{
    int i = blockIdx.x * 256 + threadIdx.x;
    if (i >= n4) return;
    int t = blockIdx.y;
    const float* src = (t == 0) ? s0 : (t == 1) ? s1 : (t == 2) ? s2 : s3;
    __half* dst = (t == 0) ? d0 : (t == 1) ? d1 : (t == 2) ? d2 : d3;
    float4 v = ((const float4*)src)[i];
    ((uint2*)dst)[i] = make_uint2(pack2h(v.x, v.y), pack2h(v.z, v.w));
}

// ===========================================================================
// Shared GEMM tiling constants (R15 proven config: BKC=32, 2-stage, 40KB)
// ===========================================================================
#define BM 128
#define BN 128
#define BKC 32
#define KTOT 1024
#define NCHUNK (KTOT / BKC)
#define LDT 40
#define TILE_B (128 * LDT * 2)     // 10240
#define STAGE1_B (2 * TILE_B)      // 20480
#define GSMEM1_SZ (2 * STAGE1_B)   // 40960

__device__ __forceinline__ uint32_t lm_addr(uint32_t base_b, int row0, int kseg0) {
    int L = threadIdx.x & 31;
    int mat = L >> 3;
    int r = (L & 7) + ((mat & 1) << 3);
    int ks = kseg0 + (mat >> 1);
    return base_b + (uint32_t)(row0 + r) * (LDT * 2) + ks * 16;
}

// ---------------------------------------------------------------------------
// Core 1-product GEMM body (device inline): acc = X @ W^T over K=1024.
// ---------------------------------------------------------------------------
__device__ __forceinline__ void gemm_body(
    const char* tbX, const char* tbW, uint32_t smb, float acc[4][4][4])
{
    const int tid = threadIdx.x;
    const int w = tid >> 5;
    const int wm = w >> 2;
    const int wn = w & 3;

    auto issue = [&](int c, int s) {
#pragma unroll
        for (int i = 0; i < 4; i++) {
            int sid = tid + 256 * i;          // 0..1023
            int tile = sid >> 9;              // 0 X, 1 W
            int r = (sid >> 2) & 127;
            int seg = sid & 3;
            const char* base = tile ? tbW : tbX;
            uint32_t sa = smb + (uint32_t)s * STAGE1_B + (uint32_t)tile * TILE_B
                        + (uint32_t)r * (LDT * 2) + seg * 16;
            const char* ga = base + (size_t)r * (KTOT * 2) + c * (BKC * 2) + seg * 16;
            cp16(sa, ga);
        }
        cp_commit();
    };

    issue(0, 0);

    for (int c = 0; c < NCHUNK; c++) {
        const int st = c & 1;
        if (c + 1 < NCHUNK) {
            issue(c + 1, st ^ 1);
            cp_wait1();
        } else {
            cp_wait0();
        }
        __syncthreads();

        const uint32_t bX = smb + (uint32_t)st * STAGE1_B;
        const uint32_t bW = bX + TILE_B;

#pragma unroll
        for (int ks = 0; ks < 2; ks++) {
            const int kseg0 = ks * 2;
            uint32_t ax[4][4], bw[4][2];
#pragma unroll
            for (int mt = 0; mt < 4; mt++)
                ldmx4(ax[mt][0], ax[mt][1], ax[mt][2], ax[mt][3],
                      lm_addr(bX, wm * 64 + mt * 16, kseg0));
#pragma unroll
            for (int np = 0; np < 2; np++) {
                uint32_t r0, r1, r2, r3;
                ldmx4(r0, r1, r2, r3, lm_addr(bW, wn * 32 + np * 16, kseg0));
                bw[np * 2 + 0][0] = r0; bw[np * 2 + 0][1] = r2;
                bw[np * 2 + 1][0] = r1; bw[np * 2 + 1][1] = r3;
            }
#pragma unroll
            for (int mt = 0; mt < 4; mt++)
#pragma unroll
                for (int nt = 0; nt < 4; nt++)
                    mma16816(acc[mt][nt], ax[mt], bw[nt]);
        }
        __syncthreads();
    }
}

// ===========================================================================
// Fused Q/K/V projection: blockIdx.z selects (X, W, out, scale); fp16 out.
// ===========================================================================
__global__ __launch_bounds__(256, 2) void gemm_proj(
    const __half* __restrict__ xq, const __half* __restrict__ xk,
    const __half* __restrict__ xv,
    const __half* __restrict__ Wq, const __half* __restrict__ Wk,
    const __half* __restrict__ Wv,
    __half* __restrict__ Q, __half* __restrict__ K, __half* __restrict__ V)
{
    extern __shared__ char dynsm[];
    const uint32_t smb = smem_u32(dynsm);
    const int which = blockIdx.z;
    const int bm = blockIdx.y * BM;
    const int bn = blockIdx.x * BN;

    const __half* X = (which == 0) ? xq : (which == 1) ? xk : xv;
    const __half* W = (which == 0) ? Wq : (which == 1) ? Wk : Wv;
    __half* O = (which == 0) ? Q : (which == 1) ? K : V;
    const float scale = (which == 0) ? SCALE_LOG2E : 1.0f;

    float acc[4][4][4];
#pragma unroll
    for (int i = 0; i < 4; i++)
#pragma unroll
        for (int j = 0; j < 4; j++)
#pragma unroll
            for (int t = 0; t < 4; t++) acc[i][j][t] = 0.f;

    gemm_body((const char*)(X + (size_t)bm * KTOT),
              (const char*)(W + (size_t)bn * KTOT), smb, acc);

    const int tid = threadIdx.x;
    const int w = tid >> 5;
    const int wm = w >> 2;
    const int wn = w & 3;
    const int lid = tid & 31;
    const int grp = lid >> 2;
    const int tig = lid & 3;
#pragma unroll
    for (int mt = 0; mt < 4; mt++) {
#pragma unroll
        for (int nt = 0; nt < 4; nt++) {
            int row = bm + wm * 64 + mt * 16 + grp;
            int col = bn + wn * 32 + nt * 8 + tig * 2;
            *(uint32_t*)(O + (size_t)row * E_ + col) =
                pack2h(acc[mt][nt][0] * scale, acc[mt][nt][1] * scale);
            *(uint32_t*)(O + (size_t)(row + 8) * E_ + col) =
                pack2h(acc[mt][nt][2] * scale, acc[mt][nt][3] * scale);
        }
    }
}

// ===========================================================================
// Output projection: C = A @ Wo^T + bias, fp32 out.
// ===========================================================================
__global__ __launch_bounds__(256, 2) void gemm_out(
    const __half* __restrict__ X, const __half* __restrict__ W,
    const float* __restrict__ bias, float* __restrict__ Cf)
{
    extern __shared__ char dynsm[];
    const uint32_t smb = smem_u32(dynsm);
    const int bm = blockIdx.y * BM;
    const int bn = blockIdx.x * BN;

    float acc[4][4][4];
#pragma unroll
    for (int i = 0; i < 4; i++)
#pragma unroll
        for (int j = 0; j < 4; j++)
#pragma unroll
            for (int t = 0; t < 4; t++) acc[i][j][t] = 0.f;

    gemm_body((const char*)(X + (size_t)bm * KTOT),
              (const char*)(W + (size_t)bn * KTOT), smb, acc);

    const int tid = threadIdx.x;
    const int w = tid >> 5;
    const int wm = w >> 2;
    const int wn = w & 3;
    const int lid = tid & 31;
    const int grp = lid >> 2;
    const int tig = lid & 3;
#pragma unroll
    for (int mt = 0; mt < 4; mt++) {
#pragma unroll
        for (int nt = 0; nt < 4; nt++) {
            int row = bm + wm * 64 + mt * 16 + grp;
            int col = bn + wn * 32 + nt * 8 + tig * 2;
            float b0 = bias[col], b1 = bias[col + 1];
            *(float2*)(Cf + (size_t)row * E_ + col) =
                make_float2(acc[mt][nt][0] + b0, acc[mt][nt][1] + b1);
            *(float2*)(Cf + (size_t)(row + 8) * E_ + col) =
                make_float2(acc[mt][nt][2] + b0, acc[mt][nt][3] + b1);
        }
    }
}

// ===========================================================================
// Tensor-core causal flash attention, fp16 single-product (R15 proven config).
// q-tile 128 rows (8 warps); S = Q K^T; O = P V; exp2 softmax.
// K/V double-buffered cp.async with wait0.
// ===========================================================================
#define ALDT 144                   // smem row stride bytes
#define AQ_TILE (128 * ALDT)       // 18432
#define AKV_TILE (64 * ALDT)       // 9216
#define AOFF_Q 0
#define AOFF_ST AQ_TILE            // 18432
#define ASTAGE (2 * AKV_TILE)      // 18432
#define ASMEM (AOFF_ST + 2 * ASTAGE)  // 55296

__device__ __forceinline__ uint32_t lda(uint32_t base, int r0, int c0) {
    int L = threadIdx.x & 31;
    int mat = L >> 3;
    int r = r0 + (L & 7) + ((mat & 1) << 3);
    int c = c0 + ((mat >> 1) << 3);
    return base + (uint32_t)r * ALDT + c * 2;
}

__global__ __launch_bounds__(256) void attn_mma(
    const __half* __restrict__ Q, const __half* __restrict__ K,
    const __half* __restrict__ V, __half* __restrict__ O)
{
    extern __shared__ char dynsm[];
    const uint32_t smb = smem_u32(dynsm);
    const int tid = threadIdx.x;
    const int w = tid >> 5;
    const int lid = tid & 31;
    const int grp = lid >> 2;
    const int tig = lid & 3;
    const int iblk = (gridDim.x - 1) - blockIdx.x;   // heavy blocks first
    const int h = blockIdx.y;
    const int b = blockIdx.z;
    const int qbase = iblk * 128;
    const int jmax = 2 * iblk + 1;
    const size_t bN = (size_t)b * N_;

    auto issue_stage = [&](int s, int kbase) {
#pragma unroll
        for (int i = 0; i < 4; i++) {
            int sid = tid + 256 * i;          // 0..1023
            int tile = sid >> 9;              // 0 K, 1 V
            int r = (sid >> 3) & 63;
            int seg = sid & 7;
            const __half* gp = tile ? V : K;
            const char* ga = (const char*)(gp + (bN + kbase + r) * E_ + h * 64)
                           + seg * 16;
            cp16(smb + AOFF_ST + (uint32_t)s * ASTAGE + (uint32_t)tile * AKV_TILE
                 + (uint32_t)r * ALDT + seg * 16, ga);
        }
        cp_commit();
    };

    // prologue: Q tile (128 rows x 64 cols) + KV stage 0
    {
#pragma unroll
        for (int i = 0; i < 4; i++) {
            int sid = tid + 256 * i;          // 0..1023
            int r = sid >> 3;
            int seg = sid & 7;
            const char* ga = (const char*)(Q + (bN + qbase + r) * E_ + h * 64)
                           + seg * 16;
            cp16(smb + AOFF_Q + (uint32_t)r * ALDT + seg * 16, ga);
        }
    }
    issue_stage(0, 0);

    uint32_t qq[4][4];
    float o[8][4];
#pragma unroll
    for (int t = 0; t < 8; t++)
#pragma unroll
        for (int c = 0; c < 4; c++) o[t][c] = 0.f;
    float mr0 = -1e30f, mr1 = -1e30f, lr0 = 0.f, lr1 = 0.f;

    for (int j = 0; j <= jmax; j++) {
        cp_wait0();
        __syncthreads();
        if (j == 0) {
#pragma unroll
            for (int kc = 0; kc < 4; kc++)
                ldmx4(qq[kc][0], qq[kc][1], qq[kc][2], qq[kc][3],
                      lda(smb + AOFF_Q, w * 16, kc * 16));
        }
        if (j < jmax) issue_stage((j + 1) & 1, (j + 1) * 64);

        const uint32_t bK = smb + AOFF_ST + (uint32_t)(j & 1) * ASTAGE;
        const uint32_t bV = bK + AKV_TILE;

        // ---- S = Q K^T (hoisted K fragments) ----
        float s[8][4];
#pragma unroll
        for (int t = 0; t < 8; t++)
#pragma unroll
            for (int c = 0; c < 4; c++) s[t][c] = 0.f;
#pragma unroll
        for (int kc = 0; kc < 4; kc++) {
            uint32_t bk[8][2];
#pragma unroll
            for (int np = 0; np < 4; np++) {
                uint32_t r0, r1, r2, r3;
                ldmx4(r0, r1, r2, r3, lda(bK, np * 16, kc * 16));
                bk[np * 2 + 0][0] = r0; bk[np * 2 + 0][1] = r2;
                bk[np * 2 + 1][0] = r1; bk[np * 2 + 1][1] = r3;
            }
#pragma unroll
            for (int t = 0; t < 8; t++) mma16816(s[t], qq[kc], bk[t]);
        }

        // ---- causal mask (only kv-blocks crossing the diagonal) ----
        if (j >= 2 * iblk) {
            const int row0 = qbase + w * 16 + grp;
            const int row1 = row0 + 8;
            const int cb = j * 64;
#pragma unroll
            for (int t = 0; t < 8; t++) {
                int col = cb + t * 8 + 2 * tig;
                if (col > row0) s[t][0] = -1e30f;
                if (col + 1 > row0) s[t][1] = -1e30f;
                if (col > row1) s[t][2] = -1e30f;
                if (col + 1 > row1) s[t][3] = -1e30f;
            }
        }

        // ---- online softmax (base-2) ----
        float m0 = -1e30f, m1 = -1e30f;
#pragma unroll
        for (int t = 0; t < 8; t++) {
            m0 = fmaxf(m0, fmaxf(s[t][0], s[t][1]));
            m1 = fmaxf(m1, fmaxf(s[t][2], s[t][3]));
        }
        m0 = fmaxf(m0, __shfl_xor_sync(0xffffffffu, m0, 1));
        m0 = fmaxf(m0, __shfl_xor_sync(0xffffffffu, m0, 2));
        m1 = fmaxf(m1, __shfl_xor_sync(0xffffffffu, m1, 1));
        m1 = fmaxf(m1, __shfl_xor_sync(0xffffffffu, m1, 2));
        float mn0 = fmaxf(mr0, m0), mn1 = fmaxf(mr1, m1);
        float a0 = exp2f(mr0 - mn0), a1 = exp2f(mr1 - mn1);
        mr0 = mn0; mr1 = mn1;
        float sum0 = 0.f, sum1 = 0.f;
#pragma unroll
        for (int t = 0; t < 8; t++) {
            s[t][0] = exp2f(s[t][0] - mn0);
            s[t][1] = exp2f(s[t][1] - mn0);
            s[t][2] = exp2f(s[t][2] - mn1);
            s[t][3] = exp2f(s[t][3] - mn1);
            sum0 += s[t][0] + s[t][1];
            sum1 += s[t][2] + s[t][3];
        }
        sum0 += __shfl_xor_sync(0xffffffffu, sum0, 1);
        sum0 += __shfl_xor_sync(0xffffffffu, sum0, 2);
        sum1 += __shfl_xor_sync(0xffffffffu, sum1, 1);
        sum1 += __shfl_xor_sync(0xffffffffu, sum1, 2);
        lr0 = lr0 * a0 + sum0;
        lr1 = lr1 * a1 + sum1;
#pragma unroll
        for (int t = 0; t < 8; t++) {
            o[t][0] *= a0; o[t][1] *= a0;
            o[t][2] *= a1; o[t][3] *= a1;
        }

        // ---- P: C-frag -> A-frag, single fp16 ----
        uint32_t ph[4][4];
#pragma unroll
        for (int kc = 0; kc < 4; kc++) {
            ph[kc][0] = pack2h(s[2 * kc][0], s[2 * kc][1]);
            ph[kc][1] = pack2h(s[2 * kc][2], s[2 * kc][3]);
            ph[kc][2] = pack2h(s[2 * kc + 1][0], s[2 * kc + 1][1]);
            ph[kc][3] = pack2h(s[2 * kc + 1][2], s[2 * kc + 1][3]);
        }

        // ---- O += P V (hoisted V fragments) ----
#pragma unroll
        for (int kc = 0; kc < 4; kc++) {
            uint32_t vv[8][2];
#pragma unroll
            for (int nd = 0; nd < 4; nd++) {
                uint32_t r0, r1, r2, r3;
                ldmx4t(r0, r1, r2, r3, lda(bV, kc * 16, nd * 16));
                vv[nd * 2 + 0][0] = r0; vv[nd * 2 + 0][1] = r1;
                vv[nd * 2 + 1][0] = r2; vv[nd * 2 + 1][1] = r3;
            }
#pragma unroll
            for (int t = 0; t < 8; t++) mma16816(o[t], ph[kc], vv[t]);
        }
    }

    // ---- epilogue: normalize, single fp16, store [B,N,E] ----
    const float i0 = 1.f / lr0, i1 = 1.f / lr1;
    const int qr0 = qbase + w * 16 + grp;
    const size_t ro0 = (bN + qr0) * E_;
    const size_t ro1 = (bN + qr0 + 8) * E_;
#pragma unroll
    for (int t = 0; t < 8; t++) {
        int col = h * 64 + t * 8 + 2 * tig;
        *(uint32_t*)(O + ro0 + col) = pack2h(o[t][0] * i0, o[t][1] * i0);
        *(uint32_t*)(O + ro1 + col) = pack2h(o[t][2] * i1, o[t][3] * i1);
    }
}

// ---------------------------------------------------------------------------
extern "C" void kernel_launch(void* const* d_in, const int* in_sizes, int n_in,
                              void* d_out, int out_size)
{
    const float* xq = (const float*)d_in[0];
    const float* xk = (const float*)d_in[1];
    const float* xv = (const float*)d_in[2];
    // d_in[3] = attn_mask (causal, recomputed analytically) — unused
    const float* Wq = (const float*)d_in[4];
    const float* Wk = (const float*)d_in[5];
    const float* Wv = (const float*)d_in[6];
    const float* Wo = (const float*)d_in[7];
    const float* bo = (const float*)d_in[8];
    float* out = (float*)d_out;

    __half *xqp, *xkp, *xvp;
    __half *Qb, *Kb, *Vb, *Ab;
    __half *Wqh, *Wkh, *Wvh, *Woh;
    cudaGetSymbolAddress((void**)&xqp, g_xq);
    cudaGetSymbolAddress((void**)&xkp, g_xk);
    cudaGetSymbolAddress((void**)&xvp, g_xv);
    cudaGetSymbolAddress((void**)&Qb, g_Q);
    cudaGetSymbolAddress((void**)&Kb, g_K);
    cudaGetSymbolAddress((void**)&Vb, g_V);
    cudaGetSymbolAddress((void**)&Ab, g_A);
    cudaGetSymbolAddress((void**)&Wqh, g_Wq);
    cudaGetSymbolAddress((void**)&Wkh, g_Wk);
    cudaGetSymbolAddress((void**)&Wvh, g_Wv);
    cudaGetSymbolAddress((void**)&Woh, g_Wo);

    cudaFuncSetAttribute(gemm_proj, cudaFuncAttributeMaxDynamicSharedMemorySize,
                         GSMEM1_SZ);
    cudaFuncSetAttribute(gemm_out, cudaFuncAttributeMaxDynamicSharedMemorySize,
                         GSMEM1_SZ);
    cudaFuncSetAttribute(attn_mma, cudaFuncAttributeMaxDynamicSharedMemorySize,
                         ASMEM);

    // Prepass conversions (fused: 2 launches)
    const int nx4 = MTOT * E_ / 4;
    const int nw4 = E_ * E_ / 4;
    dim3 cx(nx4 / 256, 3);
    convert_h3<<<cx, 256>>>(xq, xk, xv, xqp, xkp, xvp, nx4);
    dim3 cw(nw4 / 256, 4);
    convert_h4<<<cw, 256>>>(Wq, Wk, Wv, Wo, Wqh, Wkh, Wvh, Woh, nw4);

    // Fused Q/K/V projections (one launch, z selects which)
    dim3 gblock(256);
    dim3 pgrid(E_ / BN, MTOT / BM, 3);     // (8, 64, 3)
    gemm_proj<<<pgrid, gblock, GSMEM1_SZ>>>(xqp, xkp, xvp, Wqh, Wkh, Wvh,
                                            Qb, Kb, Vb);

    dim3 agrid(N_ / 128, H_, B_);          // (16, 16, 4)
    attn_mma<<<agrid, 256, ASMEM>>>(Qb, Kb, Vb, Ab);

    // Output projection -> fp32 + bias
    dim3 ogrid(E_ / BN, MTOT / BM);        // (8, 64)
    gemm_out<<<ogrid, gblock, GSMEM1_SZ>>>(Ab, Woh, bo, out);
}